// round 15
// baseline (speedup 1.0000x reference)
#include <cuda_runtime.h>
#include <cstdint>

#define NPTS 500000
#define DIM  64
#define KC   1024
#define MT   128     // points per CTA (pass 1)
#define NT   64      // centers per K-tile
#define TPB  256
#define TAU  0.0625f // fp32 margin below which we re-check in fp64

// Scratch (device globals: no allocation anywhere)
__device__ int    g_refine_cnt;
__device__ int    g_refine_idx[NPTS];
__device__ double g_m2d[KC];
__device__ float  g_m2f[KC];

// ---------------- setup: zero counter + exact ||c||^2 ----------------
__global__ void setup_kernel(const float* __restrict__ centers) {
    int k = blockIdx.x * blockDim.x + threadIdx.x;
    if (k == 0) g_refine_cnt = 0;
    if (k < KC) {
        double s = 0.0;
#pragma unroll
        for (int d = 0; d < DIM; d++) {
            double c = (double)centers[k * DIM + d];
            s = fma(c, c, s);
        }
        g_m2d[k] = s;
        g_m2f[k] = (float)s;
    }
}

// Packed fp32x2 FMA: acc.{lo,hi} += a.{lo,hi} * b.{lo,hi}
__device__ __forceinline__ void ffma2(unsigned long long& acc,
                                      unsigned long long a,
                                      unsigned long long b) {
    asm("fma.rn.f32x2 %0, %1, %2, %0;" : "+l"(acc) : "l"(a), "l"(b));
}

__device__ __forceinline__ unsigned long long pack2(float lo, float hi) {
    return (unsigned long long)__float_as_uint(lo) |
           ((unsigned long long)__float_as_uint(hi) << 32);
}

// ---------------- pass 1: register-tiled fp32x2 GEMM + top-2 argmin ----------------
__global__ __launch_bounds__(TPB, 2)
void kmeans_pass1(const float* __restrict__ x,
                  const float* __restrict__ centers,
                  float* __restrict__ out)
{
    // d-pair-major packed tiles: As[d2][m] = (x[m][2d2], x[m][2d2+1]); 48KB total
    __shared__ unsigned long long As[DIM / 2][MT];   // 32 KB
    __shared__ unsigned long long Bs[DIM / 2][NT];   // 16 KB

    const int tid     = threadIdx.x;
    const int tx      = tid & 15;    // center lane: cols {tx, tx+16, tx+32, tx+48}
    const int ty      = tid >> 4;    // point group: rows [ty*8, ty*8+8)
    const int m_block = blockIdx.x * MT;

    // ---- stage x tile: coalesced global float4 reads ----
    {
        const float4* xv = reinterpret_cast<const float4*>(x);
#pragma unroll
        for (int r = 0; r < 8; r++) {
            int flat = tid + r * TPB;       // 0..2047
            int m    = flat >> 4;           // coalesced: 16 lanes share m? no: d4 fast
            int d4   = flat & 15;
            int gm   = m_block + m;
            if (gm > NPTS - 1) gm = NPTS - 1;   // clamp; stores masked later
            float4 v = xv[(size_t)gm * (DIM / 4) + d4];
            As[d4 * 2    ][m] = pack2(v.x, v.y);
            As[d4 * 2 + 1][m] = pack2(v.z, v.w);
        }
    }

    // per-row running top-2 (v1 <= v2) and best index
    float v1[8], v2[8];
    int   i1[8];
#pragma unroll
    for (int i = 0; i < 8; i++) { v1[i] = 3.4e38f; v2[i] = 3.4e38f; i1[i] = 0; }

    const float4* cv = reinterpret_cast<const float4*>(centers);

    for (int kt = 0; kt < KC / NT; kt++) {
        if (kt) __syncthreads();
        // ---- stage center tile: k-major (conflict-free shared writes; reads hit L2) ----
#pragma unroll
        for (int r = 0; r < 4; r++) {
            int flat = tid + r * TPB;       // 0..1023
            int k    = flat & (NT - 1);
            int d4   = flat >> 6;
            float4 v = cv[(size_t)(kt * NT + k) * (DIM / 4) + d4];
            Bs[d4 * 2    ][k] = pack2(v.x, v.y);
            Bs[d4 * 2 + 1][k] = pack2(v.z, v.w);
        }
        __syncthreads();

        // ---- mainloop: 8x4 packed micro-tile ----
        unsigned long long acc[8][4];
#pragma unroll
        for (int i = 0; i < 8; i++)
#pragma unroll
            for (int j = 0; j < 4; j++) acc[i][j] = 0ull;

#pragma unroll 4
        for (int d2 = 0; d2 < DIM / 2; d2++) {
            unsigned long long a[8], b[4];
            const ulonglong2* ap =
                reinterpret_cast<const ulonglong2*>(&As[d2][ty * 8]);
#pragma unroll
            for (int h = 0; h < 4; h++) {   // 4x LDS.128, 2-addr broadcast
                ulonglong2 t = ap[h];
                a[2 * h]     = t.x;
                a[2 * h + 1] = t.y;
            }
#pragma unroll
            for (int j = 0; j < 4; j++)     // 4x LDS.64, conflict-free
                b[j] = Bs[d2][tx + 16 * j];
#pragma unroll
            for (int i = 0; i < 8; i++)
#pragma unroll
                for (int j = 0; j < 4; j++)
                    ffma2(acc[i][j], a[i], b[j]);
        }

        // ---- epilogue: fold s = m2 - 2*dot into per-thread top-2 ----
#pragma unroll
        for (int j = 0; j < 4; j++) {
            int   kg  = kt * NT + tx + 16 * j;
            float m2k = __ldg(&g_m2f[kg]);
#pragma unroll
            for (int i = 0; i < 8; i++) {
                unsigned long long u = acc[i][j];
                float lo = __uint_as_float((unsigned)u);
                float hi = __uint_as_float((unsigned)(u >> 32));
                float s  = fmaf(-2.0f, lo + hi, m2k);
                if (s < v1[i])      { v2[i] = v1[i]; v1[i] = s; i1[i] = kg; }
                else if (s < v2[i]) { v2[i] = s; }
            }
        }
    }

    // ---- merge top-2 across the 16 tx-lanes (xor stays within ty group) ----
#pragma unroll
    for (int i = 0; i < 8; i++) {
        float a1 = v1[i], a2 = v2[i];
        int   ai = i1[i];
#pragma unroll
        for (int off = 8; off > 0; off >>= 1) {
            float w1 = __shfl_xor_sync(0xffffffffu, a1, off);
            float w2 = __shfl_xor_sync(0xffffffffu, a2, off);
            int   wi = __shfl_xor_sync(0xffffffffu, ai, off);
            float n1, n2;
            int   ni;
            if (w1 < a1) { n1 = w1; ni = wi; } else { n1 = a1; ni = ai; }
            n2 = fminf(fmaxf(a1, w1), fminf(a2, w2));
            a1 = n1; a2 = n2; ai = ni;
        }
        if (tx == 0) {
            int gm = m_block + ty * 8 + i;
            if (gm < NPTS) {
                out[gm] = (float)ai;
                if (a2 - a1 < TAU) {
                    int slot = atomicAdd(&g_refine_cnt, 1);
                    g_refine_idx[slot] = gm;
                }
            }
        }
    }
}

// ---------------- pass 2: exact fp64 argmin for flagged points ----------------
__global__ __launch_bounds__(128)
void kmeans_refine(const float* __restrict__ x,
                   const float* __restrict__ centers,
                   float* __restrict__ out)
{
    __shared__ double xs[DIM];
    __shared__ double sv[128];
    __shared__ int    si[128];

    const int tid   = threadIdx.x;
    const int count = g_refine_cnt;

    for (int e = blockIdx.x; e < count; e += gridDim.x) {
        const int p = g_refine_idx[e];

        __syncthreads();
        if (tid < DIM) xs[tid] = (double)x[(size_t)p * DIM + tid];
        __syncthreads();

        double bv = 1.7976931348623157e308;
        int    bi = KC;
        for (int k = tid; k < KC; k += 128) {
            const float* c = centers + (size_t)k * DIM;
            double d0 = 0.0, d1 = 0.0;
#pragma unroll
            for (int d = 0; d < DIM; d += 2) {
                d0 = fma(xs[d],     (double)c[d],     d0);
                d1 = fma(xs[d + 1], (double)c[d + 1], d1);
            }
            double s = fma(-2.0, d0 + d1, g_m2d[k]);
            if (s < bv || (s == bv && k < bi)) { bv = s; bi = k; }
        }
        sv[tid] = bv;
        si[tid] = bi;
        __syncthreads();

#pragma unroll
        for (int off = 64; off > 0; off >>= 1) {
            if (tid < off) {
                double vo = sv[tid + off];
                int    io = si[tid + off];
                if (vo < sv[tid] || (vo == sv[tid] && io < si[tid])) {
                    sv[tid] = vo;
                    si[tid] = io;
                }
            }
            __syncthreads();
        }
        if (tid == 0) out[p] = (float)si[0];
        __syncthreads();
    }
}

extern "C" void kernel_launch(void* const* d_in, const int* in_sizes, int n_in,
                              void* d_out, int out_size) {
    const float* p0 = (const float*)d_in[0];
    const float* p1 = (const float*)d_in[1];

    const float* x       = p0;
    const float* centers = p1;
    if (n_in >= 2 && (in_sizes[0] == KC * DIM || in_sizes[0] == KC * DIM * 4)) {
        x = p1; centers = p0;
    }

    float* out = (float*)d_out;

    setup_kernel<<<(KC + 255) / 256, 256>>>(centers);
    kmeans_pass1<<<(NPTS + MT - 1) / MT, TPB>>>(x, centers, out);
    kmeans_refine<<<2048, 128>>>(x, centers, out);
}

// round 17
// speedup vs baseline: 1.0018x; 1.0018x over previous
#include <cuda_runtime.h>
#include <cstdint>

#define NPTS 500000
#define DIM  64
#define KC   1024
#define MT   128     // points per CTA (pass 1)
#define NT   64      // centers per K-tile
#define TPB  256
#define TAU  0.0625f // fp32 margin below which we re-check in fp64

// Scratch (device globals: no allocation anywhere)
__device__ int    g_refine_cnt;
__device__ int    g_refine_idx[NPTS];
__device__ double g_m2d[KC];
__device__ float  g_m2f[KC];

// ---------------- setup: zero counter + exact ||c||^2 ----------------
__global__ void setup_kernel(const float* __restrict__ centers) {
    int k = blockIdx.x * blockDim.x + threadIdx.x;
    if (k == 0) g_refine_cnt = 0;
    if (k < KC) {
        double s = 0.0;
#pragma unroll
        for (int d = 0; d < DIM; d++) {
            double c = (double)centers[k * DIM + d];
            s = fma(c, c, s);
        }
        g_m2d[k] = s;
        g_m2f[k] = (float)s;
    }
}

// Packed fp32x2 FMA: acc.{lo,hi} += a.{lo,hi} * b.{lo,hi}
__device__ __forceinline__ void ffma2(unsigned long long& acc,
                                      unsigned long long a,
                                      unsigned long long b) {
    asm("fma.rn.f32x2 %0, %1, %2, %0;" : "+l"(acc) : "l"(a), "l"(b));
}

__device__ __forceinline__ unsigned long long pack2(float lo, float hi) {
    return (unsigned long long)__float_as_uint(lo) |
           ((unsigned long long)__float_as_uint(hi) << 32);
}

// ---------------- pass 1: register-tiled fp32x2 GEMM + top-2 argmin ----------------
__global__ __launch_bounds__(TPB, 2)
void kmeans_pass1(const float* __restrict__ x,
                  const float* __restrict__ centers,
                  float* __restrict__ out)
{
    // d-pair-major packed tiles: As[d2][m] = (x[m][2d2], x[m][2d2+1]); 48KB total
    __shared__ unsigned long long As[DIM / 2][MT];   // 32 KB
    __shared__ unsigned long long Bs[DIM / 2][NT];   // 16 KB

    const int tid     = threadIdx.x;
    const int tx      = tid & 15;    // center lane: cols {tx, tx+16, tx+32, tx+48}
    const int ty      = tid >> 4;    // point group: rows [ty*8, ty*8+8)
    const int m_block = blockIdx.x * MT;

    // ---- stage x tile: coalesced global float4 reads ----
    {
        const float4* xv = reinterpret_cast<const float4*>(x);
#pragma unroll
        for (int r = 0; r < 8; r++) {
            int flat = tid + r * TPB;       // 0..2047
            int m    = flat >> 4;           // coalesced: 16 lanes share m? no: d4 fast
            int d4   = flat & 15;
            int gm   = m_block + m;
            if (gm > NPTS - 1) gm = NPTS - 1;   // clamp; stores masked later
            float4 v = xv[(size_t)gm * (DIM / 4) + d4];
            As[d4 * 2    ][m] = pack2(v.x, v.y);
            As[d4 * 2 + 1][m] = pack2(v.z, v.w);
        }
    }

    // per-row running top-2 (v1 <= v2) and best index
    float v1[8], v2[8];
    int   i1[8];
#pragma unroll
    for (int i = 0; i < 8; i++) { v1[i] = 3.4e38f; v2[i] = 3.4e38f; i1[i] = 0; }

    const float4* cv = reinterpret_cast<const float4*>(centers);

    for (int kt = 0; kt < KC / NT; kt++) {
        if (kt) __syncthreads();
        // ---- stage center tile: k-major (conflict-free shared writes; reads hit L2) ----
#pragma unroll
        for (int r = 0; r < 4; r++) {
            int flat = tid + r * TPB;       // 0..1023
            int k    = flat & (NT - 1);
            int d4   = flat >> 6;
            float4 v = cv[(size_t)(kt * NT + k) * (DIM / 4) + d4];
            Bs[d4 * 2    ][k] = pack2(v.x, v.y);
            Bs[d4 * 2 + 1][k] = pack2(v.z, v.w);
        }
        __syncthreads();

        // ---- mainloop: 8x4 packed micro-tile ----
        unsigned long long acc[8][4];
#pragma unroll
        for (int i = 0; i < 8; i++)
#pragma unroll
            for (int j = 0; j < 4; j++) acc[i][j] = 0ull;

#pragma unroll 4
        for (int d2 = 0; d2 < DIM / 2; d2++) {
            unsigned long long a[8], b[4];
            const ulonglong2* ap =
                reinterpret_cast<const ulonglong2*>(&As[d2][ty * 8]);
#pragma unroll
            for (int h = 0; h < 4; h++) {   // 4x LDS.128, 2-addr broadcast
                ulonglong2 t = ap[h];
                a[2 * h]     = t.x;
                a[2 * h + 1] = t.y;
            }
#pragma unroll
            for (int j = 0; j < 4; j++)     // 4x LDS.64, conflict-free
                b[j] = Bs[d2][tx + 16 * j];
#pragma unroll
            for (int i = 0; i < 8; i++)
#pragma unroll
                for (int j = 0; j < 4; j++)
                    ffma2(acc[i][j], a[i], b[j]);
        }

        // ---- epilogue: fold s = m2 - 2*dot into per-thread top-2 ----
#pragma unroll
        for (int j = 0; j < 4; j++) {
            int   kg  = kt * NT + tx + 16 * j;
            float m2k = __ldg(&g_m2f[kg]);
#pragma unroll
            for (int i = 0; i < 8; i++) {
                unsigned long long u = acc[i][j];
                float lo = __uint_as_float((unsigned)u);
                float hi = __uint_as_float((unsigned)(u >> 32));
                float s  = fmaf(-2.0f, lo + hi, m2k);
                if (s < v1[i])      { v2[i] = v1[i]; v1[i] = s; i1[i] = kg; }
                else if (s < v2[i]) { v2[i] = s; }
            }
        }
    }

    // ---- merge top-2 across the 16 tx-lanes (xor stays within ty group) ----
#pragma unroll
    for (int i = 0; i < 8; i++) {
        float a1 = v1[i], a2 = v2[i];
        int   ai = i1[i];
#pragma unroll
        for (int off = 8; off > 0; off >>= 1) {
            float w1 = __shfl_xor_sync(0xffffffffu, a1, off);
            float w2 = __shfl_xor_sync(0xffffffffu, a2, off);
            int   wi = __shfl_xor_sync(0xffffffffu, ai, off);
            float n1, n2;
            int   ni;
            if (w1 < a1) { n1 = w1; ni = wi; } else { n1 = a1; ni = ai; }
            n2 = fminf(fmaxf(a1, w1), fminf(a2, w2));
            a1 = n1; a2 = n2; ai = ni;
        }
        if (tx == 0) {
            int gm = m_block + ty * 8 + i;
            if (gm < NPTS) {
                out[gm] = (float)ai;
                if (a2 - a1 < TAU) {
                    int slot = atomicAdd(&g_refine_cnt, 1);
                    g_refine_idx[slot] = gm;
                }
            }
        }
    }
}

// ---------------- pass 2: exact fp64 argmin for flagged points ----------------
__global__ __launch_bounds__(128)
void kmeans_refine(const float* __restrict__ x,
                   const float* __restrict__ centers,
                   float* __restrict__ out)
{
    __shared__ double xs[DIM];
    __shared__ double sv[128];
    __shared__ int    si[128];

    const int tid   = threadIdx.x;
    const int count = g_refine_cnt;

    for (int e = blockIdx.x; e < count; e += gridDim.x) {
        const int p = g_refine_idx[e];

        __syncthreads();
        if (tid < DIM) xs[tid] = (double)x[(size_t)p * DIM + tid];
        __syncthreads();

        double bv = 1.7976931348623157e308;
        int    bi = KC;
        for (int k = tid; k < KC; k += 128) {
            const float* c = centers + (size_t)k * DIM;
            double d0 = 0.0, d1 = 0.0;
#pragma unroll
            for (int d = 0; d < DIM; d += 2) {
                d0 = fma(xs[d],     (double)c[d],     d0);
                d1 = fma(xs[d + 1], (double)c[d + 1], d1);
            }
            double s = fma(-2.0, d0 + d1, g_m2d[k]);
            if (s < bv || (s == bv && k < bi)) { bv = s; bi = k; }
        }
        sv[tid] = bv;
        si[tid] = bi;
        __syncthreads();

#pragma unroll
        for (int off = 64; off > 0; off >>= 1) {
            if (tid < off) {
                double vo = sv[tid + off];
                int    io = si[tid + off];
                if (vo < sv[tid] || (vo == sv[tid] && io < si[tid])) {
                    sv[tid] = vo;
                    si[tid] = io;
                }
            }
            __syncthreads();
        }
        if (tid == 0) out[p] = (float)si[0];
        __syncthreads();
    }
}

extern "C" void kernel_launch(void* const* d_in, const int* in_sizes, int n_in,
                              void* d_out, int out_size) {
    const float* p0 = (const float*)d_in[0];
    const float* p1 = (const float*)d_in[1];

    const float* x       = p0;
    const float* centers = p1;
    if (n_in >= 2 && (in_sizes[0] == KC * DIM || in_sizes[0] == KC * DIM * 4)) {
        x = p1; centers = p0;
    }

    float* out = (float*)d_out;

    setup_kernel<<<(KC + 255) / 256, 256>>>(centers);
    kmeans_pass1<<<(NPTS + MT - 1) / MT, TPB>>>(x, centers, out);
    kmeans_refine<<<2048, 128>>>(x, centers, out);
}